// round 17
// baseline (speedup 1.0000x reference)
#include <cuda_runtime.h>

// Pyramid Givens circuit, n = m = 512, B = 256.
// Layer t in [0,1021): gates (i,i+1) for i ≡ t (mod 2), 0 <= i <= min(t, 1020-t).
// theta index: q=(t+i)/2, tidx = q(q+1)/2 + q - i.  Gate: a'=c*a+s*b ; b'=c*b-s*a.
//
// Lane L owns wires [8L,8L+7] (h=0) and [256+8L,256+8L+7] (h=1), packed as
// (v_{w+k}, v_{w+k+4}). Upper half active only for t in [255,765]; chunks
// (28 layers) phase-split into both-halves / lower-only straight-line bodies.
// Rotation uses sub.rn.f32x2 (no sign-flip XORs). Left gates scalar via one
// v4.f32 load. 3-buffer cp.async.bulk pipeline; smem loads non-volatile with
// 32-bit base + compile-time immediate (mbar_wait "memory" clobber fences them).

#define N_WIRES   512
#define CHUNK_L   28
#define NCHUNK    37                   // 37*28 = 1036 layers (tail identity)
#define T_PAD     (NCHUNK * CHUNK_L)   // 1036
#define LAYER_B   2560                 // rot 2048 + left 512
#define LEFT_OFF  2048
#define CHUNK_B   (CHUNK_L * LAYER_B)  // 71680
#define STAGE_B   (2 * LAYER_B)        // 5120
#define MID_LO    9                    // chunks 9..27 cover t in [252,783] ⊇ [255,765]
#define MID_HI    27

typedef unsigned long long ull;

// Per layer t (stride LAYER_B):
//   [0,2048):    rot double2 {c2,s2}, entry at h*1024 + r*512 + lane*16
//   [2048,2560): left-gate 16B per lane: {lfc_L, lfc_U, lfs_L, lfs_U}
//                (sines pre-negated). Gate (w-1, w) per half.
// Inactive gates stored as identity.
__device__ __align__(128) char g_tab[(size_t)T_PAD * LAYER_B];   // ~2.65 MB

__device__ __forceinline__ float2 cs_of(const float* __restrict__ th, int t, int i) {
    if (t <= 1020 && i >= 0 && i <= t && i <= 1020 - t && (((i ^ t) & 1) == 0)) {
        int q = (t + i) >> 1;
        int tidx = (q * (q + 1)) / 2 + q - i;
        float s, c;
        __sincosf(th[tidx], &s, &c);    // |theta| <= pi
        return make_float2(c, s);
    }
    return make_float2(1.0f, 0.0f);
}

// 512 threads = 4 layers per block.
__global__ void build_cs_kernel(const float* __restrict__ thetas) {
    int t    = blockIdx.x * 4 + (threadIdx.x >> 7);
    if (t >= T_PAD) return;
    int h    = (threadIdx.x >> 6) & 1;
    int r    = (threadIdx.x >> 5) & 1;
    int lane = threadIdx.x & 31;
    int w    = 256 * h + 8 * lane;
    int ilo, ihi;
    if ((t & 1) == 0) { ilo = w + 2 * r;     ihi = ilo + 4; }
    else              { ilo = w + 2 * r + 1; ihi = ilo + 4; }
    float2 a = cs_of(thetas, t, ilo);
    float2 b = cs_of(thetas, t, ihi);
    char* base = g_tab + (size_t)t * LAYER_B;
    float2* dst = reinterpret_cast<float2*>(base + h * 1024 + r * 512 + lane * 16);
    dst[0] = make_float2(a.x, b.x);   // c2
    dst[1] = make_float2(a.y, b.y);   // s2
    if (r == 0) {
        float2 lf = cs_of(thetas, t, w - 1);
        char* lp = base + LEFT_OFF + lane * 16;
        *reinterpret_cast<float*>(lp + h * 4)     = lf.x;    // lfc_L / lfc_U
        *reinterpret_cast<float*>(lp + 8 + h * 4) = -lf.y;   // lfs pre-negated
    }
}

// ---- f32x2 helpers ----
__device__ __forceinline__ ull mul2(ull a, ull b) {
    ull d; asm("mul.rn.f32x2 %0, %1, %2;" : "=l"(d) : "l"(a), "l"(b)); return d;
}
__device__ __forceinline__ ull fma2(ull a, ull b, ull c) {
    ull d; asm("fma.rn.f32x2 %0, %1, %2, %3;" : "=l"(d) : "l"(a), "l"(b), "l"(c)); return d;
}
__device__ __forceinline__ ull sub2(ull a, ull b) {
    ull d; asm("sub.rn.f32x2 %0, %1, %2;" : "=l"(d) : "l"(a), "l"(b)); return d;
}
__device__ __forceinline__ float lo_f(ull p) {
    float lo; asm("{ .reg .b32 hi_; mov.b64 {%0, hi_}, %1; }" : "=f"(lo) : "l"(p)); return lo;
}
__device__ __forceinline__ float hi_f(ull p) {
    float hi; asm("{ .reg .b32 lo_; mov.b64 {lo_, %0}, %1; }" : "=f"(hi) : "l"(p)); return hi;
}
__device__ __forceinline__ ull pk(float lo, float hi) {
    ull d; asm("mov.b64 %0, {%1, %2};" : "=l"(d) : "f"(lo), "f"(hi)); return d;
}

#define FULLM 0xffffffffu

// Packed Givens, no negation: a' = c*a + s*b ; b' = c*b - s*a
__device__ __forceinline__ void rotp(ull& a, ull& b, ull c2, ull s2) {
    ull t1 = mul2(s2, b);
    ull na = fma2(c2, a, t1);
    ull t2 = mul2(s2, a);
    ull t3 = mul2(c2, b);
    b = sub2(t3, t2);
    a = na;
}

// ---- 32-bit shared loads, immediate offsets, NON-volatile (ordering by the
// "memory" clobber in mbar_wait / __syncthreads; within a chunk data is const)
template<int OFF>
__device__ __forceinline__ void lds_u64x2(unsigned base, ull& x, ull& y) {
    asm("ld.shared.v2.u64 {%0, %1}, [%2+%3];"
        : "=l"(x), "=l"(y) : "r"(base), "n"(OFF));
}
template<int OFF>
__device__ __forceinline__ void lds_f32x4(unsigned base, float& x, float& y,
                                          float& z, float& w) {
    asm("ld.shared.v4.f32 {%0, %1, %2, %3}, [%4+%5];"
        : "=f"(x), "=f"(y), "=f"(z), "=f"(w) : "r"(base), "n"(OFF));
}

// ---- bulk-copy / mbarrier helpers ----
__device__ __forceinline__ unsigned s2u(const void* p) {
    return (unsigned)__cvta_generic_to_shared(p);
}
__device__ __forceinline__ void mbar_init(unsigned mbar, unsigned cnt) {
    asm volatile("mbarrier.init.shared.b64 [%0], %1;" :: "r"(mbar), "r"(cnt) : "memory");
}
__device__ __forceinline__ void mbar_expect_tx(unsigned mbar, unsigned bytes) {
    asm volatile("mbarrier.arrive.expect_tx.shared.b64 _, [%0], %1;"
                 :: "r"(mbar), "r"(bytes) : "memory");
}
__device__ __forceinline__ void bulk_g2s(unsigned dst, const void* src, unsigned bytes,
                                         unsigned mbar) {
    asm volatile("cp.async.bulk.shared::cluster.global.mbarrier::complete_tx::bytes "
                 "[%0], [%1], %2, [%3];"
                 :: "r"(dst), "l"(src), "r"(bytes), "r"(mbar) : "memory");
}
__device__ __forceinline__ void mbar_wait(unsigned mbar, unsigned parity) {
    unsigned done;
    asm volatile(
        "{\n\t.reg .pred p;\n\t"
        "mbarrier.try_wait.parity.acquire.cta.shared::cta.b64 p, [%1], %2;\n\t"
        "selp.b32 %0, 1, 0, p;\n\t}"
        : "=r"(done) : "r"(mbar), "r"(parity) : "memory");
    if (!done) {
        asm volatile(
            "{\n\t.reg .pred P1;\n\t"
            "WL_%=:\n\t"
            "mbarrier.try_wait.parity.acquire.cta.shared::cta.b64 P1, [%0], %1, 0x989680;\n\t"
            "@P1 bra.uni WD_%=;\n\t"
            "bra.uni WL_%=;\n\t"
            "WD_%=:\n\t}"
            :: "r"(mbar), "r"(parity) : "memory");
    }
}
__device__ __forceinline__ void fence_async_shared() {
    asm volatile("fence.proxy.async.shared::cta;" ::: "memory");
}

struct CoefH {
    ull Ec0, Es0, Ec1, Es1;
    ull Oc0, Os0, Oc1, Os1;
    float lfcL, lfcU, lfsL, lfsU;   // scalar left-gate; sines pre-negated
};

#define LDROT(d, S, H) do {                                                      \
    lds_u64x2<(S)*STAGE_B + (H)*1024          >(rbase, (d).Ec0, (d).Es0);        \
    lds_u64x2<(S)*STAGE_B + (H)*1024 + 512    >(rbase, (d).Ec1, (d).Es1);        \
    lds_u64x2<(S)*STAGE_B + LAYER_B + (H)*1024      >(rbase, (d).Oc0, (d).Os0);  \
    lds_u64x2<(S)*STAGE_B + LAYER_B + (H)*1024 + 512>(rbase, (d).Oc1, (d).Os1);  \
} while (0)
#define LDLEFT(d, S) \
    lds_f32x4<(S)*STAGE_B + LAYER_B + LEFT_OFF>(rbase, (d).lfcL, (d).lfcU, (d).lfsL, (d).lfsU)

#define LDB(dA, dB, S) do { LDROT(dA, S, 0); LDROT(dB, S, 1); LDLEFT(dA, S); } while (0)
#define LDL(dA, S)     do { LDROT(dA, S, 0); LDLEFT(dA, S); } while (0)

__device__ __forceinline__ void stage_lower(ull* L, CoefH& A, int lane) {
    rotp(L[0], L[1], A.Ec0, A.Es0);
    rotp(L[2], L[3], A.Ec1, A.Es1);
    float pl0  = lo_f(L[0]);
    float pl15 = hi_f(L[3]);
    float vnL = __shfl_down_sync(FULLM, pl0, 1);   // lane31 junk safe (identity gate)
    float lvL = __shfl_up_sync  (FULLM, pl15, 1);  // lane0 junk safe (identity left gate)
    float baseL = A.lfcL * pl0;
    rotp(L[1], L[2], A.Oc0, A.Os0);
    ull Ql = pk(hi_f(L[0]), vnL);
    rotp(L[3], Ql, A.Oc1, A.Os1);
    float nv0 = fmaf(A.lfsL, lvL, baseL);          // lfs pre-negated
    L[0] = pk(nv0, lo_f(Ql));
}

// Both-halves stage; even rotps interleaved L/U so all shuffle sources are
// ready early; seam via index-mode wraparound shuffles; scalar left-gates.
__device__ __forceinline__ void stage_both(ull* L, ull* U, CoefH& A, CoefH& Bc,
                                           int lane, int idxn, int idxp) {
    rotp(L[0], L[1], A.Ec0, A.Es0);
    rotp(U[0], U[1], Bc.Ec0, Bc.Es0);
    float pl0 = lo_f(L[0]);
    float pu0 = lo_f(U[0]);
    float y   = (lane == 0) ? pu0 : pl0;
    float vnL = __shfl_sync(FULLM, y, idxn);       // lane31 <- v256
    float vnU = __shfl_down_sync(FULLM, pu0, 1);   // lane31 junk safe (511/512 identity)

    rotp(L[2], L[3], A.Ec1, A.Es1);
    rotp(U[2], U[3], Bc.Ec1, Bc.Es1);
    float pl15 = hi_f(L[3]);
    float pu15 = hi_f(U[3]);
    float z   = (lane == 31) ? pl15 : pu15;
    float lvU = __shfl_sync(FULLM, z, idxp);       // lane0  <- v255
    float lvL = __shfl_up_sync(FULLM, pl15, 1);    // lane0 junk safe

    rotp(L[1], L[2], A.Oc0, A.Os0);
    ull Ql = pk(hi_f(L[0]), vnL);
    rotp(L[3], Ql, A.Oc1, A.Os1);
    float nv0 = fmaf(A.lfsL, lvL, A.lfcL * pl0);
    L[0] = pk(nv0, lo_f(Ql));

    rotp(U[1], U[2], Bc.Oc0, Bc.Os0);
    ull Qu = pk(hi_f(U[0]), vnU);
    rotp(U[3], Qu, Bc.Oc1, Bc.Os1);
    float nu0 = fmaf(A.lfsU, lvU, A.lfcU * pu0);
    U[0] = pk(nu0, lo_f(Qu));
}

__global__ void __launch_bounds__(64, 1) apply_kernel(
    const float* __restrict__ x,
    const float* __restrict__ bias,
    float* __restrict__ out)
{
    extern __shared__ __align__(128) char sbuf[];       // 3 * CHUNK_B dynamic
    __shared__ __align__(8) unsigned long long mbar[3];

    const int tid  = threadIdx.x;
    const int lane = tid & 31;
    const int row  = blockIdx.x * 2 + (tid >> 5);
    const int idxn = (lane + 1) & 31;
    const int idxp = (lane - 1) & 31;

    if (tid == 0) {
        mbar_init(s2u(&mbar[0]), 1);
        mbar_init(s2u(&mbar[1]), 1);
        mbar_init(s2u(&mbar[2]), 1);
    }

    ull L[4], U[4];
    {
        const float4* xl = reinterpret_cast<const float4*>(x + (size_t)row * N_WIRES + 8 * lane);
        const float4* xu = reinterpret_cast<const float4*>(x + (size_t)row * N_WIRES + 256 + 8 * lane);
        float4 a0 = xl[0], a1 = xl[1], b0 = xu[0], b1 = xu[1];
        L[0] = pk(a0.x, a1.x); L[1] = pk(a0.y, a1.y);
        L[2] = pk(a0.z, a1.z); L[3] = pk(a0.w, a1.w);
        U[0] = pk(b0.x, b1.x); U[1] = pk(b0.y, b1.y);
        U[2] = pk(b0.z, b1.z); U[3] = pk(b0.w, b1.w);
    }

    __syncthreads();

    if (tid == 0) {
        #pragma unroll
        for (int pc = 0; pc < 3; ++pc) {
            unsigned mb = s2u(&mbar[pc]);
            mbar_expect_tx(mb, CHUNK_B);
            bulk_g2s(s2u(sbuf) + pc * CHUNK_B, g_tab + (size_t)pc * CHUNK_B, CHUNK_B, mb);
        }
    }

    const unsigned sb = s2u(sbuf);
    unsigned rbase = sb + lane * 16;

    CoefH A0, A1, B0, B1;
    int rb = 0;
    #pragma unroll 1
    for (int c = 0; c < NCHUNK; ++c) {
        mbar_wait(s2u(&mbar[rb]), (unsigned)((c / 3) & 1));

        if (c >= MID_LO && c <= MID_HI) {
            LDB(A0, B0, 0);
            LDB(A1, B1, 1);   stage_both(L, U, A0, B0, lane, idxn, idxp);
            LDB(A0, B0, 2);   stage_both(L, U, A1, B1, lane, idxn, idxp);
            LDB(A1, B1, 3);   stage_both(L, U, A0, B0, lane, idxn, idxp);
            LDB(A0, B0, 4);   stage_both(L, U, A1, B1, lane, idxn, idxp);
            LDB(A1, B1, 5);   stage_both(L, U, A0, B0, lane, idxn, idxp);
            LDB(A0, B0, 6);   stage_both(L, U, A1, B1, lane, idxn, idxp);
            LDB(A1, B1, 7);   stage_both(L, U, A0, B0, lane, idxn, idxp);
            LDB(A0, B0, 8);   stage_both(L, U, A1, B1, lane, idxn, idxp);
            LDB(A1, B1, 9);   stage_both(L, U, A0, B0, lane, idxn, idxp);
            LDB(A0, B0, 10);  stage_both(L, U, A1, B1, lane, idxn, idxp);
            LDB(A1, B1, 11);  stage_both(L, U, A0, B0, lane, idxn, idxp);
            LDB(A0, B0, 12);  stage_both(L, U, A1, B1, lane, idxn, idxp);
            LDB(A1, B1, 13);  stage_both(L, U, A0, B0, lane, idxn, idxp);
            stage_both(L, U, A1, B1, lane, idxn, idxp);
        } else {
            LDL(A0, 0);
            LDL(A1, 1);    stage_lower(L, A0, lane);
            LDL(A0, 2);    stage_lower(L, A1, lane);
            LDL(A1, 3);    stage_lower(L, A0, lane);
            LDL(A0, 4);    stage_lower(L, A1, lane);
            LDL(A1, 5);    stage_lower(L, A0, lane);
            LDL(A0, 6);    stage_lower(L, A1, lane);
            LDL(A1, 7);    stage_lower(L, A0, lane);
            LDL(A0, 8);    stage_lower(L, A1, lane);
            LDL(A1, 9);    stage_lower(L, A0, lane);
            LDL(A0, 10);   stage_lower(L, A1, lane);
            LDL(A1, 11);   stage_lower(L, A0, lane);
            LDL(A0, 12);   stage_lower(L, A1, lane);
            LDL(A1, 13);   stage_lower(L, A0, lane);
            stage_lower(L, A1, lane);
        }

        __syncthreads();
        if (tid == 0 && c + 3 < NCHUNK) {
            fence_async_shared();
            unsigned mb = s2u(&mbar[rb]);
            mbar_expect_tx(mb, CHUNK_B);
            bulk_g2s(sb + rb * CHUNK_B, g_tab + (size_t)(c + 3) * CHUNK_B, CHUNK_B, mb);
        }

        rb = (rb == 2) ? 0 : rb + 1;
        rbase += CHUNK_B;
        if (rb == 0) rbase -= 3 * CHUNK_B;
    }

    {
        const float* bl = bias + 8 * lane;
        float* ol = out + (size_t)row * N_WIRES + 8 * lane;
        float4 bb0 = *reinterpret_cast<const float4*>(bl);
        float4 bb1 = *reinterpret_cast<const float4*>(bl + 4);
        float4 bb2 = *reinterpret_cast<const float4*>(bl + 256);
        float4 bb3 = *reinterpret_cast<const float4*>(bl + 260);
        float4 o0, o1, o2, o3;
        o0.x = lo_f(L[0]) + bb0.x; o0.y = lo_f(L[1]) + bb0.y;
        o0.z = lo_f(L[2]) + bb0.z; o0.w = lo_f(L[3]) + bb0.w;
        o1.x = hi_f(L[0]) + bb1.x; o1.y = hi_f(L[1]) + bb1.y;
        o1.z = hi_f(L[2]) + bb1.z; o1.w = hi_f(L[3]) + bb1.w;
        o2.x = lo_f(U[0]) + bb2.x; o2.y = lo_f(U[1]) + bb2.y;
        o2.z = lo_f(U[2]) + bb2.z; o2.w = lo_f(U[3]) + bb2.w;
        o3.x = hi_f(U[0]) + bb3.x; o3.y = hi_f(U[1]) + bb3.y;
        o3.z = hi_f(U[2]) + bb3.z; o3.w = hi_f(U[3]) + bb3.w;
        *reinterpret_cast<float4*>(ol)       = o0;
        *reinterpret_cast<float4*>(ol + 4)   = o1;
        *reinterpret_cast<float4*>(ol + 256) = o2;
        *reinterpret_cast<float4*>(ol + 260) = o3;
    }
}

extern "C" void kernel_launch(void* const* d_in, const int* in_sizes, int n_in,
                              void* d_out, int out_size) {
    const float* x      = (const float*)d_in[0];
    const float* thetas = (const float*)d_in[1];
    const float* bias   = (const float*)d_in[2];
    float* out = (float*)d_out;

    build_cs_kernel<<<(T_PAD + 3) / 4, 512>>>(thetas);

    cudaFuncSetAttribute(apply_kernel,
                         cudaFuncAttributeMaxDynamicSharedMemorySize, 3 * CHUNK_B);

    int B = in_sizes[0] / N_WIRES;   // 256
    apply_kernel<<<B / 2, 64, 3 * CHUNK_B>>>(x, bias, out);
}